// round 1
// baseline (speedup 1.0000x reference)
#include <cuda_runtime.h>

#define HD 128
#define MAXN 40000
#define MAXE 640000
#define MAXR 8

// ---- scratch (static device globals; no allocation) ----
__device__ float g_w[(size_t)MAXR*HD*HD];        // per-relation weights [R,D,H]
__device__ float g_xw[(size_t)MAXR*MAXN*HD];     // X @ w[r]  [R,N,H]  (164 MB)
__device__ float g_h[(size_t)MAXN*HD];           // layer-1 output h
__device__ float g_nbr[(size_t)MAXN*HD];         // layer-2 neighbor sum
__device__ int   g_deg[MAXN];
__device__ int   g_rs[MAXN+1];                   // CSR row starts (by dst)
__device__ int   g_cur[MAXN];                    // scatter cursors
__device__ int   g_csrc[MAXE];                   // permuted src
__device__ int   g_ctype[MAXE];                  // permuted type

// ---- w[r,d,h] = sum_b comp[r,b]*basis[b,d,h] ----
__global__ void k_compute_w(const float* __restrict__ comp,
                            const float* __restrict__ basis, int R, int B) {
    int rd = blockIdx.x;          // r*HD + d
    int r = rd / HD;
    int h = threadIdx.x;
    int d = rd % HD;
    float s = 0.f;
    for (int b = 0; b < B; b++)
        s += comp[r*B + b] * basis[((size_t)b*HD + d)*HD + h];
    g_w[(size_t)rd*HD + h] = s;
}

__global__ void k_zero(int* p, int n) {
    int i = blockIdx.x*blockDim.x + threadIdx.x;
    if (i < n) p[i] = 0;
}

__global__ void k_hist(const int* __restrict__ ei, int E) {
    int e = blockIdx.x*blockDim.x + threadIdx.x;
    if (e >= E) return;
    atomicAdd(&g_deg[ei[E + e]], 1);
}

// single-block Hillis-Steele scan over deg -> row_start, cursor
__global__ void k_scan(int n) {
    __shared__ int sd[1024];
    __shared__ int soff;
    int t = threadIdx.x;
    if (t == 0) { soff = 0; g_rs[0] = 0; }
    __syncthreads();
    for (int base = 0; base < n; base += 1024) {
        int i = base + t;
        int v = (i < n) ? g_deg[i] : 0;
        sd[t] = v;
        __syncthreads();
        for (int off = 1; off < 1024; off <<= 1) {
            int a = (t >= off) ? sd[t - off] : 0;
            __syncthreads();
            sd[t] += a;
            __syncthreads();
        }
        if (i < n) { g_rs[i+1] = soff + sd[t]; g_cur[i] = soff + sd[t] - v; }
        __syncthreads();
        if (t == 0) soff += sd[1023];
        __syncthreads();
    }
}

__global__ void k_scatter(const int* __restrict__ ei, const int* __restrict__ et, int E) {
    int e = blockIdx.x*blockDim.x + threadIdx.x;
    if (e >= E) return;
    int dst = ei[E + e];
    int p = atomicAdd(&g_cur[dst], 1);
    g_csrc[p]  = ei[e];
    g_ctype[p] = et[e];
}

// ---- fp32 SGEMM: C[z] (+)= A @ B[z] (+ A2 @ B2) (+ bias), N=K=128 fixed ----
// 128x128 tile, 256 threads, 8x8 per thread (split as 2x f4 in each dim)
template<int TWO, int ACC, int BIAS>
__global__ void __launch_bounds__(256)
k_gemm(const float* __restrict__ A,  const float* __restrict__ B,
       const float* __restrict__ A2, const float* __restrict__ B2,
       const float* __restrict__ bias, float* __restrict__ C,
       int M, size_t bStrideZ, size_t cStrideZ)
{
    B += blockIdx.z * bStrideZ;
    C += blockIdx.z * cStrideZ;
    int row0 = blockIdx.x * 128;
    int tid = threadIdx.x;
    int tx = tid & 15, ty = tid >> 4;

    __shared__ float As[8][128];   // [k][m]
    __shared__ float Bs[8][128];   // [k][n]

    float acc[8][8];
#pragma unroll
    for (int i = 0; i < 8; i++)
#pragma unroll
        for (int j = 0; j < 8; j++) acc[i][j] = 0.f;

    int mIdx = tid >> 1;              // 0..127
    int kg   = (tid & 1) * 4;         // 0 or 4
    int kb   = tid >> 5;              // 0..7
    int nb   = (tid & 31) * 4;        // 0..124
    bool aValid = (row0 + mIdx) < M;

    const float* Ap = A;
    const float* Bp = B;
#pragma unroll
    for (int pass = 0; pass < (TWO ? 2 : 1); ++pass) {
        if (pass == 1) { Ap = A2; Bp = B2; }
        for (int kc = 0; kc < 16; kc++) {
            int k0 = kc * 8;
            float4 av = make_float4(0.f, 0.f, 0.f, 0.f);
            if (aValid) av = *(const float4*)(Ap + (size_t)(row0 + mIdx)*HD + k0 + kg);
            float4 bv = *(const float4*)(Bp + (size_t)(k0 + kb)*HD + nb);
            __syncthreads();
            As[kg+0][mIdx] = av.x; As[kg+1][mIdx] = av.y;
            As[kg+2][mIdx] = av.z; As[kg+3][mIdx] = av.w;
            *(float4*)&Bs[kb][nb] = bv;
            __syncthreads();
#pragma unroll
            for (int k = 0; k < 8; k++) {
                float4 a0 = *(const float4*)&As[k][ty*4];
                float4 a1 = *(const float4*)&As[k][64 + ty*4];
                float4 b0 = *(const float4*)&Bs[k][tx*4];
                float4 b1 = *(const float4*)&Bs[k][64 + tx*4];
                float a8[8] = {a0.x,a0.y,a0.z,a0.w,a1.x,a1.y,a1.z,a1.w};
                float b8[8] = {b0.x,b0.y,b0.z,b0.w,b1.x,b1.y,b1.z,b1.w};
#pragma unroll
                for (int i = 0; i < 8; i++)
#pragma unroll
                    for (int j = 0; j < 8; j++)
                        acc[i][j] += a8[i] * b8[j];
            }
        }
    }

    float bb[8];
#pragma unroll
    for (int j = 0; j < 8; j++) {
        int c = (j < 4) ? tx*4 + j : 64 + tx*4 + (j - 4);
        bb[j] = BIAS ? bias[c] : 0.f;
    }
#pragma unroll
    for (int i = 0; i < 8; i++) {
        int r = (i < 4) ? ty*4 + i : 64 + ty*4 + (i - 4);
        int row = row0 + r;
        if (row < M) {
            float* cp0 = C + (size_t)row*HD + tx*4;
            float* cp1 = C + (size_t)row*HD + 64 + tx*4;
            float4 v0 = make_float4(acc[i][0]+bb[0], acc[i][1]+bb[1],
                                    acc[i][2]+bb[2], acc[i][3]+bb[3]);
            float4 v1 = make_float4(acc[i][4]+bb[4], acc[i][5]+bb[5],
                                    acc[i][6]+bb[6], acc[i][7]+bb[7]);
            if (ACC) {
                float4 o0 = *(const float4*)cp0, o1 = *(const float4*)cp1;
                v0.x += o0.x; v0.y += o0.y; v0.z += o0.z; v0.w += o0.w;
                v1.x += o1.x; v1.y += o1.y; v1.z += o1.z; v1.w += o1.w;
            }
            *(float4*)cp0 = v0;
            *(float4*)cp1 = v1;
        }
    }
}

// ---- layer-1 aggregation: warp per dst node, mean of xw[type,src,:] ----
__global__ void k_agg1(int N) {
    int gt = blockIdx.x*blockDim.x + threadIdx.x;
    int node = gt >> 5, lane = gt & 31;
    if (node >= N) return;
    int a = g_rs[node], b = g_rs[node+1];
    float4 acc = make_float4(0.f, 0.f, 0.f, 0.f);
    for (int i = a; i < b; i++) {
        int s  = g_csrc[i];
        int tp = g_ctype[i];
        const float4* r = (const float4*)(g_xw + ((size_t)tp*N + s)*HD);
        float4 v = r[lane];
        acc.x += v.x; acc.y += v.y; acc.z += v.z; acc.w += v.w;
    }
    float inv = 1.f / fmaxf((float)(b - a), 1.f);
    acc.x *= inv; acc.y *= inv; acc.z *= inv; acc.w *= inv;
    ((float4*)(g_h + (size_t)node*HD))[lane] = acc;
}

// ---- layer-2 aggregation: warp per dst node, sum of h[src,:] ----
__global__ void k_agg2(int N) {
    int gt = blockIdx.x*blockDim.x + threadIdx.x;
    int node = gt >> 5, lane = gt & 31;
    if (node >= N) return;
    int a = g_rs[node], b = g_rs[node+1];
    float4 acc = make_float4(0.f, 0.f, 0.f, 0.f);
    for (int i = a; i < b; i++) {
        int s = g_csrc[i];
        const float4* r = (const float4*)(g_h + (size_t)s*HD);
        float4 v = r[lane];
        acc.x += v.x; acc.y += v.y; acc.z += v.z; acc.w += v.w;
    }
    ((float4*)(g_nbr + (size_t)node*HD))[lane] = acc;
}

extern "C" void kernel_launch(void* const* d_in, const int* in_sizes, int n_in,
                              void* d_out, int out_size) {
    const float* x       = (const float*)d_in[0];
    const int*   ei      = (const int*)  d_in[1];
    const int*   et      = (const int*)  d_in[3];
    const float* basis   = (const float*)d_in[4];
    const float* comp    = (const float*)d_in[5];
    const float* root    = (const float*)d_in[6];
    const float* bias1   = (const float*)d_in[7];
    const float* w_rel   = (const float*)d_in[8];
    const float* w_root2 = (const float*)d_in[9];
    const float* bias2   = (const float*)d_in[10];
    float* out = (float*)d_out;

    int N = in_sizes[0] / HD;
    int E = in_sizes[2];
    int B = in_sizes[4] / (HD * HD);
    int R = in_sizes[5] / B;

    float *p_w, *p_xw, *p_h, *p_nbr;
    int *p_deg;
    cudaGetSymbolAddress((void**)&p_w,   g_w);
    cudaGetSymbolAddress((void**)&p_xw,  g_xw);
    cudaGetSymbolAddress((void**)&p_h,   g_h);
    cudaGetSymbolAddress((void**)&p_nbr, g_nbr);
    cudaGetSymbolAddress((void**)&p_deg, g_deg);

    // per-relation weights
    k_compute_w<<<R*HD, HD>>>(comp, basis, R, B);

    // CSR by dst
    k_zero<<<(N+255)/256, 256>>>(p_deg, N);
    k_hist<<<(E+255)/256, 256>>>(ei, E);
    k_scan<<<1, 1024>>>(N);
    k_scatter<<<(E+255)/256, 256>>>(ei, et, E);

    int gx = (N + 127) / 128;

    // xw[r] = X @ w[r]   (grid.z = R)
    k_gemm<0,0,0><<<dim3(gx,1,R), 256>>>(x, p_w, nullptr, nullptr, nullptr,
                                         p_xw, N, (size_t)HD*HD, (size_t)N*HD);
    // h = mean_agg(xw)  then  h += X @ root + bias1
    k_agg1<<<(N*32 + 255)/256, 256>>>(N);
    k_gemm<0,1,1><<<dim3(gx,1,1), 256>>>(x, root, nullptr, nullptr, bias1,
                                         p_h, N, 0, 0);
    // nbr = sum_agg(h)
    k_agg2<<<(N*32 + 255)/256, 256>>>(N);
    // out = nbr @ w_rel + h @ w_root2 + bias2
    k_gemm<1,0,1><<<dim3(gx,1,1), 256>>>(p_nbr, w_rel, p_h, w_root2, bias2,
                                         out, N, 0, 0);
}

// round 3
// speedup vs baseline: 1.1199x; 1.1199x over previous
#include <cuda_runtime.h>
#include <cuda_bf16.h>
#include <cstdint>

#define HD 128
#define MAXN 40000
#define MAXE 640000
#define MAXR 8

/* ---------------- scratch (static device globals; no allocation) ------------- */
__device__ float g_w[MAXR * HD * HD];                 // per-relation weights [R][D][H]
__device__ float g_xw[(size_t)MAXR * MAXN * HD];      // X @ w[r]  (164 MB)
__device__ float g_h[(size_t)MAXN * HD];              // layer-1 output
__device__ float g_nbr[(size_t)MAXN * HD];            // layer-2 neighbor sum
__device__ int   g_deg[MAXN], g_rs[MAXN + 1], g_cur[MAXN];
__device__ int   g_csrc[MAXE], g_ctype[MAXE];
__device__ int   g_bsum[64], g_boff[64];
/* B operand images: B^T layout [slot][term(hi/lo)][n=128][k=136(pad)] bf16
   slots: 0..7 = w[r], 8 = root, 9 = w_rel, 10 = w_root2 */
#define BPITCH 136
#define BTILE  (128 * BPITCH)             /* 17408 ushort per tile */
__device__ unsigned short g_bimg[11 * 2 * BTILE];

/* ---------------- helpers ---------------------------------------------------- */
__device__ __forceinline__ uint32_t smem_u32(const void* p) {
    uint32_t a;
    asm("{ .reg .u64 t; cvta.to.shared.u64 t, %1; cvt.u32.u64 %0, t; }" : "=r"(a) : "l"(p));
    return a;
}
__device__ __forceinline__ void bsplit(float v, unsigned short& h, unsigned short& l) {
    __nv_bfloat16 bh = __float2bfloat16(v);
    h = __bfloat16_as_ushort(bh);
    l = __bfloat16_as_ushort(__float2bfloat16(v - __bfloat162float(bh)));
}

#define LDSM4(r, addr)                                                             \
    asm volatile("ldmatrix.sync.aligned.m8n8.x4.shared.b16 {%0,%1,%2,%3}, [%4];"   \
        : "=r"((r)[0]), "=r"((r)[1]), "=r"((r)[2]), "=r"((r)[3]) : "r"(addr))

#define MMA16816(c, a, b0, b1)                                                     \
    asm volatile("mma.sync.aligned.m16n8k16.row.col.f32.bf16.bf16.f32 "            \
        "{%0,%1,%2,%3}, {%4,%5,%6,%7}, {%8,%9}, {%0,%1,%2,%3};"                    \
        : "+f"((c)[0]), "+f"((c)[1]), "+f"((c)[2]), "+f"((c)[3])                   \
        : "r"((a)[0]), "r"((a)[1]), "r"((a)[2]), "r"((a)[3]), "r"(b0), "r"(b1))

/* ---------------- small prep kernels ----------------------------------------- */
__global__ void k_compute_w(const float* __restrict__ comp,
                            const float* __restrict__ basis, int R, int B) {
    int rd = blockIdx.x, h = threadIdx.x;
    int r = rd / HD, d = rd % HD;
    float s = 0.f;
    for (int b = 0; b < B; b++)
        s += comp[r * B + b] * basis[((size_t)b * HD + d) * HD + h];
    g_w[(size_t)rd * HD + h] = s;
}

/* B images: img[slot][t][n][k] = split(W[k][n]) */
__global__ void k_prep_b(const float* __restrict__ root, const float* __restrict__ wrel,
                         const float* __restrict__ wroot2) {
    int slot = blockIdx.x;
    const float* W = (slot < 8) ? (g_w + (size_t)slot * HD * HD)
                   : (slot == 8) ? root : (slot == 9) ? wrel : wroot2;
    unsigned short* hi = g_bimg + (size_t)(slot * 2 + 0) * BTILE;
    unsigned short* lo = g_bimg + (size_t)(slot * 2 + 1) * BTILE;
    for (int i = threadIdx.x; i < 128 * BPITCH; i += blockDim.x) {
        int n = i / BPITCH, k = i % BPITCH;
        float v = (k < HD) ? W[(size_t)k * HD + n] : 0.f;
        unsigned short h, l;
        bsplit(v, h, l);
        hi[i] = h;
        lo[i] = l;
    }
}

/* ---------------- CSR build -------------------------------------------------- */
__global__ void k_zero(int* p, int n) {
    int i = blockIdx.x * blockDim.x + threadIdx.x;
    if (i < n) p[i] = 0;
}
__global__ void k_hist(const int* __restrict__ ei, int E) {
    int e = blockIdx.x * blockDim.x + threadIdx.x;
    if (e < E) atomicAdd(&g_deg[ei[E + e]], 1);
}
__global__ void k_scan_a(int n) {
    __shared__ int sd[1024];
    int b = blockIdx.x, t = threadIdx.x, i = b * 1024 + t;
    int v = (i < n) ? g_deg[i] : 0;
    sd[t] = v; __syncthreads();
    for (int off = 1; off < 1024; off <<= 1) {
        int a = (t >= off) ? sd[t - off] : 0;
        __syncthreads(); sd[t] += a; __syncthreads();
    }
    if (i < n) g_rs[i + 1] = sd[t];
    if (t == 1023) g_bsum[b] = sd[t];
}
__global__ void k_scan_b(int nblk) {
    if (threadIdx.x == 0) {
        int s = 0;
        for (int b = 0; b < nblk; b++) { g_boff[b] = s; s += g_bsum[b]; }
    }
}
__global__ void k_scan_c(int n) {
    int i = blockIdx.x * blockDim.x + threadIdx.x;
    if (i == 0) g_rs[0] = 0;
    if (i < n) {
        int v = g_rs[i + 1] + g_boff[i >> 10];
        g_rs[i + 1] = v;
        g_cur[i] = v - g_deg[i];
    }
}
__global__ void k_scatter(const int* __restrict__ ei, const int* __restrict__ et, int E) {
    int e = blockIdx.x * blockDim.x + threadIdx.x;
    if (e >= E) return;
    int dst = ei[E + e];
    int p = atomicAdd(&g_cur[dst], 1);
    g_csrc[p] = ei[e];
    g_ctype[p] = et[e];
}

/* ---------------- split-bf16 mma.sync GEMM ----------------------------------- */
/* C[z] = sum_p A_p @ B_p^T (+bias). Tile 128x128, K=128 smem-resident.
   8 warps in 4x2 grid, warp tile 32x64. A loaded f32 and split on the fly.   */
#define APITCHB 272                /* 136 bf16 * 2B per row */
#define SM_AH 0
#define SM_AL 34816
#define SM_BH 69632
#define SM_BL 104448
#define SM_TOT 139264

template<int TWO, int ACC, int BIAS>
__global__ void __launch_bounds__(256) k_mma(
    const float* __restrict__ A0, const float* __restrict__ A1,
    int bslot0, int bslot1, int zslotstride,
    const float* __restrict__ bias, float* __restrict__ C, size_t cStrideZ, int M)
{
    extern __shared__ unsigned char sm[];
    uint32_t sbase = smem_u32(sm);
    int tid = threadIdx.x, lane = tid & 31, wid = tid >> 5;
    int row0 = blockIdx.x * 128;
    C += (size_t)blockIdx.z * cStrideZ;

    int wr = wid >> 1, wc = wid & 1;
    int mrow0 = wr * 32, ncol0 = wc * 64;

    float acc[2][8][4];
#pragma unroll
    for (int a = 0; a < 2; a++)
#pragma unroll
        for (int b = 0; b < 8; b++)
#pragma unroll
            for (int c = 0; c < 4; c++) acc[a][b][c] = 0.f;

#pragma unroll
    for (int p = 0; p <= TWO; p++) {
        const float* Ap = p ? A1 : A0;
        int slot = p ? bslot1 : (bslot0 + (int)blockIdx.z * zslotstride);

        if (p) __syncthreads();
        /* load A tile: f32 -> split bf16 hi/lo, pitch 136 (zero-padded) */
        for (int i = tid; i < 128 * 34; i += 256) {
            int r = i / 34, c4 = i % 34;
            float4 v = make_float4(0.f, 0.f, 0.f, 0.f);
            if (c4 < 32 && row0 + r < M)
                v = ((const float4*)(Ap + (size_t)(row0 + r) * HD))[c4];
            unsigned short h0, l0, h1, l1, h2, l2, h3, l3;
            bsplit(v.x, h0, l0); bsplit(v.y, h1, l1);
            bsplit(v.z, h2, l2); bsplit(v.w, h3, l3);
            uint2 ph = make_uint2((uint32_t)h0 | ((uint32_t)h1 << 16),
                                  (uint32_t)h2 | ((uint32_t)h3 << 16));
            uint2 pl = make_uint2((uint32_t)l0 | ((uint32_t)l1 << 16),
                                  (uint32_t)l2 | ((uint32_t)l3 << 16));
            *(uint2*)(sm + SM_AH + r * APITCHB + c4 * 8) = ph;
            *(uint2*)(sm + SM_AL + r * APITCHB + c4 * 8) = pl;
        }
        /* load B tiles (already split + padded in gmem) */
        {
            const uint4* bh = (const uint4*)(g_bimg + (size_t)(slot * 2 + 0) * BTILE);
            const uint4* bl = (const uint4*)(g_bimg + (size_t)(slot * 2 + 1) * BTILE);
            uint4* dh = (uint4*)(sm + SM_BH);
            uint4* dl = (uint4*)(sm + SM_BL);
            for (int i = tid; i < 2176; i += 256) { dh[i] = bh[i]; dl[i] = bl[i]; }
        }
        __syncthreads();

#pragma unroll
        for (int ks = 0; ks < 8; ks++) {
            uint32_t koff = ks * 32 + (lane >> 4) * 16;
            uint32_t ra[2][4], rl[2][4];
#pragma unroll
            for (int mf = 0; mf < 2; mf++) {
                uint32_t arow = (uint32_t)(mrow0 + mf * 16 + (lane & 15)) * APITCHB + koff;
                LDSM4(ra[mf], sbase + SM_AH + arow);
                LDSM4(rl[mf], sbase + SM_AL + arow);
            }
#pragma unroll
            for (int nf2 = 0; nf2 < 4; nf2++) {
                uint32_t brow = (uint32_t)(ncol0 + nf2 * 16 + (lane & 15)) * APITCHB + koff;
                uint32_t bh[4], bl[4];
                LDSM4(bh, sbase + SM_BH + brow);
                LDSM4(bl, sbase + SM_BL + brow);
#pragma unroll
                for (int mf = 0; mf < 2; mf++) {
#pragma unroll
                    for (int nfr = 0; nfr < 2; nfr++) {
                        float* c = acc[mf][nf2 * 2 + nfr];
                        MMA16816(c, ra[mf], bh[nfr], bh[nfr + 2]);   /* hi*hi */
                        MMA16816(c, rl[mf], bh[nfr], bh[nfr + 2]);   /* lo*hi */
                        MMA16816(c, ra[mf], bl[nfr], bl[nfr + 2]);   /* hi*lo */
                    }
                }
            }
        }
    }

    /* epilogue */
    int g = lane >> 2, tc = lane & 3;
#pragma unroll
    for (int mf = 0; mf < 2; mf++) {
#pragma unroll
        for (int nf = 0; nf < 8; nf++) {
            int col = ncol0 + (nf >> 1) * 16 + (nf & 1) * 8 + tc * 2;
            float bx = 0.f, by = 0.f;
            if (BIAS) { bx = bias[col]; by = bias[col + 1]; }
            int ra_ = row0 + mrow0 + mf * 16 + g;
            int rb_ = ra_ + 8;
            float* c = acc[mf][nf];
            if (ra_ < M) {
                float2 o = make_float2(c[0] + bx, c[1] + by);
                float2* cp = (float2*)(C + (size_t)ra_ * HD + col);
                if (ACC) { float2 old = *cp; o.x += old.x; o.y += old.y; }
                *cp = o;
            }
            if (rb_ < M) {
                float2 o = make_float2(c[2] + bx, c[3] + by);
                float2* cp = (float2*)(C + (size_t)rb_ * HD + col);
                if (ACC) { float2 old = *cp; o.x += old.x; o.y += old.y; }
                *cp = o;
            }
        }
    }
}

/* ---------------- aggregation kernels ----------------------------------------- */
/* layer-1: h[node] += mean_edges xw[type, src, :]  (h pre-filled with X@root+b1) */
__global__ void k_agg1(int N) {
    int gt = blockIdx.x * blockDim.x + threadIdx.x;
    int node = gt >> 5, lane = gt & 31;
    if (node >= N) return;
    int a = g_rs[node], b = g_rs[node + 1];
    float4 acc = make_float4(0.f, 0.f, 0.f, 0.f);
    for (int i = a; i < b; i++) {
        int s = g_csrc[i], tp = g_ctype[i];
        float4 v = ((const float4*)(g_xw + ((size_t)tp * N + s) * HD))[lane];
        acc.x += v.x; acc.y += v.y; acc.z += v.z; acc.w += v.w;
    }
    float inv = 1.f / fmaxf((float)(b - a), 1.f);
    float4* hp = (float4*)(g_h + (size_t)node * HD);
    float4 cur = hp[lane];
    cur.x += acc.x * inv; cur.y += acc.y * inv;
    cur.z += acc.z * inv; cur.w += acc.w * inv;
    hp[lane] = cur;
}

/* layer-2: nbr[node] = sum h[src] */
__global__ void k_agg2(int N) {
    int gt = blockIdx.x * blockDim.x + threadIdx.x;
    int node = gt >> 5, lane = gt & 31;
    if (node >= N) return;
    int a = g_rs[node], b = g_rs[node + 1];
    float4 acc = make_float4(0.f, 0.f, 0.f, 0.f);
    for (int i = a; i < b; i++) {
        float4 v = ((const float4*)(g_h + (size_t)g_csrc[i] * HD))[lane];
        acc.x += v.x; acc.y += v.y; acc.z += v.z; acc.w += v.w;
    }
    ((float4*)(g_nbr + (size_t)node * HD))[lane] = acc;
}

/* ---------------- host -------------------------------------------------------- */
extern "C" void kernel_launch(void* const* d_in, const int* in_sizes, int n_in,
                              void* d_out, int out_size) {
    const float* x       = (const float*)d_in[0];
    const int*   ei      = (const int*)  d_in[1];
    const int*   et      = (const int*)  d_in[3];
    const float* basis   = (const float*)d_in[4];
    const float* comp    = (const float*)d_in[5];
    const float* root    = (const float*)d_in[6];
    const float* bias1   = (const float*)d_in[7];
    const float* w_rel   = (const float*)d_in[8];
    const float* w_root2 = (const float*)d_in[9];
    const float* bias2   = (const float*)d_in[10];
    float* out = (float*)d_out;

    int N = in_sizes[0] / HD;
    int E = in_sizes[2];
    int B = in_sizes[4] / (HD * HD);
    int R = in_sizes[5] / B;
    int Mt = (N + 127) / 128;

    float *p_xw, *p_h, *p_nbr;
    int *p_deg;
    cudaGetSymbolAddress((void**)&p_xw,  g_xw);
    cudaGetSymbolAddress((void**)&p_h,   g_h);
    cudaGetSymbolAddress((void**)&p_nbr, g_nbr);
    cudaGetSymbolAddress((void**)&p_deg, g_deg);

    cudaFuncSetAttribute(k_mma<0,0,0>, cudaFuncAttributeMaxDynamicSharedMemorySize, SM_TOT);
    cudaFuncSetAttribute(k_mma<0,0,1>, cudaFuncAttributeMaxDynamicSharedMemorySize, SM_TOT);
    cudaFuncSetAttribute(k_mma<1,0,1>, cudaFuncAttributeMaxDynamicSharedMemorySize, SM_TOT);

    /* weights + B operand images */
    k_compute_w<<<R * HD, HD>>>(comp, basis, R, B);
    k_prep_b<<<11, 256>>>(root, w_rel, w_root2);

    /* CSR by dst */
    int nblk = (N + 1023) / 1024;
    k_zero<<<(N + 255) / 256, 256>>>(p_deg, N);
    k_hist<<<(E + 255) / 256, 256>>>(ei, E);
    k_scan_a<<<nblk, 1024>>>(N);
    k_scan_b<<<1, 32>>>(nblk);
    k_scan_c<<<nblk, 1024>>>(N);
    k_scatter<<<(E + 255) / 256, 256>>>(ei, et, E);

    /* G1a: xw[r] = X @ w[r]  (z = relation) */
    k_mma<0,0,0><<<dim3(Mt, 1, R), 256, SM_TOT>>>(x, nullptr, 0, 0, 1,
                                                  nullptr, p_xw, (size_t)N * HD, N);
    /* G1b: h = X @ root + bias1 */
    k_mma<0,0,1><<<dim3(Mt, 1, 1), 256, SM_TOT>>>(x, nullptr, 8, 0, 0,
                                                  bias1, p_h, 0, N);
    /* h += mean aggregation */
    k_agg1<<<(N * 32 + 255) / 256, 256>>>(N);
    /* nbr = sum aggregation */
    k_agg2<<<(N * 32 + 255) / 256, 256>>>(N);
    /* out = nbr @ w_rel + h @ w_root2 + bias2 */
    k_mma<1,0,1><<<dim3(Mt, 1, 1), 256, SM_TOT>>>(p_nbr, p_h, 9, 10, 0,
                                                  bias2, out, 0, N);
}

// round 4
// speedup vs baseline: 1.4701x; 1.3127x over previous
#include <cuda_runtime.h>
#include <cuda_bf16.h>
#include <cstdint>

#define HD 128
#define MAXN 40000
#define MAXR 8
#define MAXE 640000
#define MPADC (((MAXN + 127) / 128) * 128)      /* 40064 */

/* ---------------- scratch (static device globals; no allocation) ------------- */
__device__ float g_w[MAXR * HD * HD];            // per-relation weights [R][D][H]
__device__ float g_h[(size_t)MPADC * HD];        // layer-1 output (f32)
__device__ int   g_deg[MAXN], g_rs[MAXN + 1], g_cur[MAXN];
__device__ int   g_csrc[MAXE], g_ctype[MAXE];
__device__ int   g_bsum[64], g_boff[64];
/* A operand images (pre-split bf16, row pitch 128):
   layer-1: chunks 0..7 = S_r (mean-scaled per-relation sums), chunk 8 = X   */
__device__ unsigned short g_shi[(size_t)9 * MPADC * HD];
__device__ unsigned short g_slo[(size_t)9 * MPADC * HD];
/* layer-2: chunk 0 = nbr, chunk 1 = h */
__device__ unsigned short g_a2hi[(size_t)2 * MPADC * HD];
__device__ unsigned short g_a2lo[(size_t)2 * MPADC * HD];
/* B operand images: B^T layout [slot][term(hi/lo)][n=128][k pitch 136] bf16
   slots: 0..7 = w[r], 8 = root, 9 = w_rel, 10 = w_root2 */
#define BPITCH 136
#define BTILE  (128 * BPITCH)
__device__ unsigned short g_bimg[11 * 2 * BTILE];

/* ---------------- helpers ---------------------------------------------------- */
__device__ __forceinline__ uint32_t smem_u32(const void* p) {
    uint32_t a;
    asm("{ .reg .u64 t; cvta.to.shared.u64 t, %1; cvt.u32.u64 %0, t; }" : "=r"(a) : "l"(p));
    return a;
}
__device__ __forceinline__ void bsplit(float v, unsigned short& h, unsigned short& l) {
    __nv_bfloat16 bh = __float2bfloat16(v);
    h = __bfloat16_as_ushort(bh);
    l = __bfloat16_as_ushort(__float2bfloat16(v - __bfloat162float(bh)));
}
__device__ __forceinline__ uint32_t pack2(unsigned short a, unsigned short b) {
    return (uint32_t)a | ((uint32_t)b << 16);
}

#define LDSM4(r, addr)                                                             \
    asm volatile("ldmatrix.sync.aligned.m8n8.x4.shared.b16 {%0,%1,%2,%3}, [%4];"   \
        : "=r"((r)[0]), "=r"((r)[1]), "=r"((r)[2]), "=r"((r)[3]) : "r"(addr))

#define MMA16816(c, a, b0, b1)                                                     \
    asm volatile("mma.sync.aligned.m16n8k16.row.col.f32.bf16.bf16.f32 "            \
        "{%0,%1,%2,%3}, {%4,%5,%6,%7}, {%8,%9}, {%0,%1,%2,%3};"                    \
        : "+f"((c)[0]), "+f"((c)[1]), "+f"((c)[2]), "+f"((c)[3])                   \
        : "r"((a)[0]), "r"((a)[1]), "r"((a)[2]), "r"((a)[3]), "r"(b0), "r"(b1))

/* ---------------- prep kernels ------------------------------------------------ */
__global__ void k_compute_w(const float* __restrict__ comp,
                            const float* __restrict__ basis, int R, int B) {
    int rd = blockIdx.x, h = threadIdx.x;
    int r = rd / HD, d = rd % HD;
    float s = 0.f;
    for (int b = 0; b < B; b++)
        s += comp[r * B + b] * basis[((size_t)b * HD + d) * HD + h];
    g_w[(size_t)rd * HD + h] = s;
}

/* B images: img[slot][t][n][k] = split(W[k][n]) (K inner, pitch 136, pad zeroed) */
__global__ void k_prep_b(const float* __restrict__ root, const float* __restrict__ wrel,
                         const float* __restrict__ wroot2) {
    int slot = blockIdx.x;
    const float* W = (slot < 8) ? (g_w + (size_t)slot * HD * HD)
                   : (slot == 8) ? root : (slot == 9) ? wrel : wroot2;
    unsigned short* hi = g_bimg + (size_t)(slot * 2 + 0) * BTILE;
    unsigned short* lo = g_bimg + (size_t)(slot * 2 + 1) * BTILE;
    for (int i = threadIdx.x; i < 128 * BPITCH; i += blockDim.x) {
        int n = i / BPITCH, k = i % BPITCH;
        float v = (k < HD) ? W[(size_t)k * HD + n] : 0.f;
        unsigned short h, l;
        bsplit(v, h, l);
        hi[i] = h;
        lo[i] = l;
    }
}

/* X -> split bf16 image at chunk base (zero-padded rows >= N) */
__global__ void k_prep_x(const float* __restrict__ x, int N, int mpad,
                         unsigned short* __restrict__ hi, unsigned short* __restrict__ lo) {
    int t = blockIdx.x * blockDim.x + threadIdx.x;
    if (t >= mpad * 32) return;
    int m = t >> 5, k4 = t & 31;
    float4 v = make_float4(0.f, 0.f, 0.f, 0.f);
    if (m < N) v = ((const float4*)x)[(size_t)m * 32 + k4];
    unsigned short h0, l0, h1, l1, h2, l2, h3, l3;
    bsplit(v.x, h0, l0); bsplit(v.y, h1, l1);
    bsplit(v.z, h2, l2); bsplit(v.w, h3, l3);
    size_t idx = (size_t)m * HD + k4 * 4;
    *(uint2*)&hi[idx] = make_uint2(pack2(h0, h1), pack2(h2, h3));
    *(uint2*)&lo[idx] = make_uint2(pack2(l0, l1), pack2(l2, l3));
}

/* ---------------- CSR build -------------------------------------------------- */
__global__ void k_zero(int* p, int n) {
    int i = blockIdx.x * blockDim.x + threadIdx.x;
    if (i < n) p[i] = 0;
}
__global__ void k_hist(const int* __restrict__ ei, int E) {
    int e = blockIdx.x * blockDim.x + threadIdx.x;
    if (e < E) atomicAdd(&g_deg[ei[E + e]], 1);
}
__global__ void k_scan_a(int n) {
    __shared__ int sd[1024];
    int b = blockIdx.x, t = threadIdx.x, i = b * 1024 + t;
    int v = (i < n) ? g_deg[i] : 0;
    sd[t] = v; __syncthreads();
    for (int off = 1; off < 1024; off <<= 1) {
        int a = (t >= off) ? sd[t - off] : 0;
        __syncthreads(); sd[t] += a; __syncthreads();
    }
    if (i < n) g_rs[i + 1] = sd[t];
    if (t == 1023) g_bsum[b] = sd[t];
}
__global__ void k_scan_b(int nblk) {
    if (threadIdx.x == 0) {
        int s = 0;
        for (int b = 0; b < nblk; b++) { g_boff[b] = s; s += g_bsum[b]; }
    }
}
__global__ void k_scan_c(int n) {
    int i = blockIdx.x * blockDim.x + threadIdx.x;
    if (i == 0) g_rs[0] = 0;
    if (i < n) {
        int v = g_rs[i + 1] + g_boff[i >> 10];
        g_rs[i + 1] = v;
        g_cur[i] = v - g_deg[i];
    }
}
__global__ void k_scatter(const int* __restrict__ ei, const int* __restrict__ et, int E) {
    int e = blockIdx.x * blockDim.x + threadIdx.x;
    if (e >= E) return;
    int dst = ei[E + e];
    int p = atomicAdd(&g_cur[dst], 1);
    g_csrc[p] = ei[e];
    g_ctype[p] = et[e];
}

/* ---------------- S builder: per-(dst,relation) mean sums of x ---------------- */
/* warp per node; smem slab [8 relations][128] f32 per warp; writes split-bf16
   S images (chunks 0..R-1), mean-scaled; zero rows for pad nodes             */
__global__ void __launch_bounds__(256) k_aggx(const float* __restrict__ x,
                                              int N, int mpad, size_t chStride) {
    __shared__ float sw[8][8 * HD];
    int gt = blockIdx.x * blockDim.x + threadIdx.x;
    int node = gt >> 5, lane = gt & 31, w = (threadIdx.x >> 5);
    if (node >= mpad) return;
    float* acc = sw[w];
    float4 z = make_float4(0.f, 0.f, 0.f, 0.f);
#pragma unroll
    for (int r = 0; r < 8; r++) ((float4*)acc)[r * 32 + lane] = z;

    int a = 0, b = 0;
    if (node < N) { a = g_rs[node]; b = g_rs[node + 1]; }
    for (int i = a; i < b; i++) {
        int s = g_csrc[i], r = g_ctype[i];
        float4 v = ((const float4*)x)[(size_t)s * 32 + lane];
        float4* p = (float4*)&acc[r * HD + lane * 4];
        float4 o = *p;
        o.x += v.x; o.y += v.y; o.z += v.z; o.w += v.w;
        *p = o;
    }
    float inv = 1.f / fmaxf((float)(b - a), 1.f);
#pragma unroll
    for (int r = 0; r < 8; r++) {
        float4 v = ((float4*)acc)[r * 32 + lane];
        v.x *= inv; v.y *= inv; v.z *= inv; v.w *= inv;
        unsigned short h0, l0, h1, l1, h2, l2, h3, l3;
        bsplit(v.x, h0, l0); bsplit(v.y, h1, l1);
        bsplit(v.z, h2, l2); bsplit(v.w, h3, l3);
        size_t idx = (size_t)r * chStride + (size_t)node * HD + lane * 4;
        *(uint2*)&g_shi[idx] = make_uint2(pack2(h0, h1), pack2(h2, h3));
        *(uint2*)&g_slo[idx] = make_uint2(pack2(l0, l1), pack2(l2, l3));
    }
}

/* ---------------- layer-2 neighbor sum: writes nbr split images --------------- */
__global__ void __launch_bounds__(256) k_agg2(int N, int mpad) {
    int gt = blockIdx.x * blockDim.x + threadIdx.x;
    int node = gt >> 5, lane = gt & 31;
    if (node >= mpad) return;
    float4 acc = make_float4(0.f, 0.f, 0.f, 0.f);
    if (node < N) {
        int a = g_rs[node], b = g_rs[node + 1];
        for (int i = a; i < b; i++) {
            float4 v = ((const float4*)(g_h + (size_t)g_csrc[i] * HD))[lane];
            acc.x += v.x; acc.y += v.y; acc.z += v.z; acc.w += v.w;
        }
    }
    unsigned short h0, l0, h1, l1, h2, l2, h3, l3;
    bsplit(acc.x, h0, l0); bsplit(acc.y, h1, l1);
    bsplit(acc.z, h2, l2); bsplit(acc.w, h3, l3);
    size_t idx = (size_t)node * HD + lane * 4;
    *(uint2*)&g_a2hi[idx] = make_uint2(pack2(h0, h1), pack2(h2, h3));
    *(uint2*)&g_a2lo[idx] = make_uint2(pack2(l0, l1), pack2(l2, l3));
}

/* ---------------- split-bf16 mma.sync GEMM (M-tile 64, 2 CTA/SM) -------------- */
/* C = (sum_c Achunk_c @ Bslot_{bslot0+c}^T) + bias ; K = 128*nch              */
#define SM_AH 0
#define SM_AL 17408
#define SM_BH 34816
#define SM_BL 69632
#define SM_TOT 104448
#define APITCHB 272

template<int WIMG>
__global__ void __launch_bounds__(256) k_mma(
    const unsigned short* __restrict__ aHi, const unsigned short* __restrict__ aLo,
    size_t aStride, int nch, int bslot0, const float* __restrict__ bias,
    float* __restrict__ Cf, unsigned short* __restrict__ imgHi,
    unsigned short* __restrict__ imgLo, int M)
{
    extern __shared__ unsigned char sm[];
    uint32_t sbase = smem_u32(sm);
    int tid = threadIdx.x, lane = tid & 31, wid = tid >> 5;
    int row0 = blockIdx.x * 64;
    int wr = wid & 1, wc = wid >> 1;
    int mrow0 = wr * 32, ncol0 = wc * 32;

    float acc[2][4][4];
#pragma unroll
    for (int a = 0; a < 2; a++)
#pragma unroll
        for (int b = 0; b < 4; b++)
#pragma unroll
            for (int c = 0; c < 4; c++) acc[a][b][c] = 0.f;

    for (int ch = 0; ch < nch; ch++) {
        if (ch) __syncthreads();
        /* A chunk: 64 rows x 128 bf16 (hi+lo), gmem pitch 128 -> smem pitch 136 */
        const unsigned short* ah = aHi + (size_t)ch * aStride + (size_t)row0 * HD;
        const unsigned short* al = aLo + (size_t)ch * aStride + (size_t)row0 * HD;
        for (int i = tid; i < 1024; i += 256) {
            int r = i >> 4, c = i & 15;
            *(uint4*)(sm + SM_AH + r * APITCHB + c * 16) = *(const uint4*)(ah + (size_t)r * HD + c * 8);
            *(uint4*)(sm + SM_AL + r * APITCHB + c * 16) = *(const uint4*)(al + (size_t)r * HD + c * 8);
        }
        /* B chunk: padded tile, linear copy */
        {
            int slot = bslot0 + ch;
            const uint4* bh = (const uint4*)(g_bimg + (size_t)(slot * 2 + 0) * BTILE);
            const uint4* bl = (const uint4*)(g_bimg + (size_t)(slot * 2 + 1) * BTILE);
            uint4* dh = (uint4*)(sm + SM_BH);
            uint4* dl = (uint4*)(sm + SM_BL);
            for (int i = tid; i < 2176; i += 256) { dh[i] = bh[i]; dl[i] = bl[i]; }
        }
        __syncthreads();

#pragma unroll
        for (int ks = 0; ks < 8; ks++) {
            uint32_t koff = ks * 32 + (lane >> 4) * 16;
            uint32_t ra[2][4], rl[2][4];
#pragma unroll
            for (int mf = 0; mf < 2; mf++) {
                uint32_t arow = (uint32_t)(mrow0 + mf * 16 + (lane & 15)) * APITCHB + koff;
                LDSM4(ra[mf], sbase + SM_AH + arow);
                LDSM4(rl[mf], sbase + SM_AL + arow);
            }
#pragma unroll
            for (int nf2 = 0; nf2 < 2; nf2++) {
                uint32_t brow = (uint32_t)(ncol0 + nf2 * 16 + (lane & 15)) * APITCHB + koff;
                uint32_t bh[4], bl[4];
                LDSM4(bh, sbase + SM_BH + brow);
                LDSM4(bl, sbase + SM_BL + brow);
#pragma unroll
                for (int mf = 0; mf < 2; mf++) {
#pragma unroll
                    for (int nfr = 0; nfr < 2; nfr++) {
                        float* c = acc[mf][nf2 * 2 + nfr];
                        MMA16816(c, ra[mf], bh[nfr], bh[nfr + 2]);   /* hi*hi */
                        MMA16816(c, rl[mf], bh[nfr], bh[nfr + 2]);   /* lo*hi */
                        MMA16816(c, ra[mf], bl[nfr], bl[nfr + 2]);   /* hi*lo */
                    }
                }
            }
        }
    }

    /* epilogue */
    int g = lane >> 2, tc = lane & 3;
#pragma unroll
    for (int mf = 0; mf < 2; mf++) {
#pragma unroll
        for (int nf = 0; nf < 4; nf++) {
            int col = ncol0 + (nf >> 1) * 16 + (nf & 1) * 8 + tc * 2;
            float bx = bias[col], by = bias[col + 1];
            float* c = acc[mf][nf];
            int rowA = row0 + mrow0 + mf * 16 + g;
            int rowB = rowA + 8;
            float v0 = c[0] + bx, v1 = c[1] + by;
            float v2 = c[2] + bx, v3 = c[3] + by;
            if (rowA < M) *(float2*)(Cf + (size_t)rowA * HD + col) = make_float2(v0, v1);
            if (rowB < M) *(float2*)(Cf + (size_t)rowB * HD + col) = make_float2(v2, v3);
            if (WIMG) {
                unsigned short h0, l0, h1, l1;
                bsplit(v0, h0, l0); bsplit(v1, h1, l1);
                *(uint32_t*)&imgHi[(size_t)rowA * HD + col] = pack2(h0, h1);
                *(uint32_t*)&imgLo[(size_t)rowA * HD + col] = pack2(l0, l1);
                bsplit(v2, h0, l0); bsplit(v3, h1, l1);
                *(uint32_t*)&imgHi[(size_t)rowB * HD + col] = pack2(h0, h1);
                *(uint32_t*)&imgLo[(size_t)rowB * HD + col] = pack2(l0, l1);
            }
        }
    }
}

/* ---------------- host -------------------------------------------------------- */
extern "C" void kernel_launch(void* const* d_in, const int* in_sizes, int n_in,
                              void* d_out, int out_size) {
    const float* x       = (const float*)d_in[0];
    const int*   ei      = (const int*)  d_in[1];
    const int*   et      = (const int*)  d_in[3];
    const float* basis   = (const float*)d_in[4];
    const float* comp    = (const float*)d_in[5];
    const float* root    = (const float*)d_in[6];
    const float* bias1   = (const float*)d_in[7];
    const float* w_rel   = (const float*)d_in[8];
    const float* w_root2 = (const float*)d_in[9];
    const float* bias2   = (const float*)d_in[10];
    float* out = (float*)d_out;

    int N = in_sizes[0] / HD;
    int E = in_sizes[2];
    int B = in_sizes[4] / (HD * HD);
    int R = in_sizes[5] / B;
    int mpad = ((N + 127) / 128) * 128;
    size_t chStride = (size_t)mpad * HD;

    float *p_h;
    int *p_deg;
    unsigned short *p_shi, *p_slo, *p_a2hi, *p_a2lo;
    cudaGetSymbolAddress((void**)&p_h,    g_h);
    cudaGetSymbolAddress((void**)&p_deg,  g_deg);
    cudaGetSymbolAddress((void**)&p_shi,  g_shi);
    cudaGetSymbolAddress((void**)&p_slo,  g_slo);
    cudaGetSymbolAddress((void**)&p_a2hi, g_a2hi);
    cudaGetSymbolAddress((void**)&p_a2lo, g_a2lo);

    cudaFuncSetAttribute(k_mma<0>, cudaFuncAttributeMaxDynamicSharedMemorySize, SM_TOT);
    cudaFuncSetAttribute(k_mma<1>, cudaFuncAttributeMaxDynamicSharedMemorySize, SM_TOT);

    /* weights + operand images */
    k_compute_w<<<R * HD, HD>>>(comp, basis, R, B);
    k_prep_b<<<11, 256>>>(root, w_rel, w_root2);
    k_prep_x<<<(mpad * 32 + 255) / 256, 256>>>(x, N, mpad,
                                               p_shi + (size_t)R * chStride,
                                               p_slo + (size_t)R * chStride);

    /* CSR by dst */
    int nblk = (N + 1023) / 1024;
    k_zero<<<(N + 255) / 256, 256>>>(p_deg, N);
    k_hist<<<(E + 255) / 256, 256>>>(ei, E);
    k_scan_a<<<nblk, 1024>>>(N);
    k_scan_b<<<1, 32>>>(nblk);
    k_scan_c<<<nblk, 1024>>>(N);
    k_scatter<<<(E + 255) / 256, 256>>>(ei, et, E);

    /* per-(dst,relation) mean sums -> S images */
    k_aggx<<<mpad / 8, 256>>>(x, N, mpad, chStride);

    /* layer-1 fused GEMM: h = [S | X] @ [w;root] + bias1, also emit h image */
    k_mma<1><<<mpad / 64, 256, SM_TOT>>>(p_shi, p_slo, chStride, R + 1, 0, bias1,
                                         p_h, p_a2hi + chStride, p_a2lo + chStride, N);
    /* nbr = sum_j h[j] -> nbr image (chunk 0) */
    k_agg2<<<mpad / 8, 256>>>(N, mpad);
    /* layer-2 GEMM: out = [nbr | h] @ [w_rel; w_root2] + bias2 */
    k_mma<0><<<mpad / 64, 256, SM_TOT>>>(p_a2hi, p_a2lo, chStride, 2, 9, bias2,
                                         out, nullptr, nullptr, N);
}